// round 9
// baseline (speedup 1.0000x reference)
#include <cuda_runtime.h>
#include <cstdint>

#define G  256
#define NV 512
#define NE 4096
#define FI 64
#define FO 64
#define FH 32              // feature half
#define NC 16
#define KFLAT (NV*FO)      // 32768

__device__ float g_h [(size_t)G*NV*FO];          // 33.5 MB
__device__ float g_part[(size_t)G*512*NC];       // 8 MB: [g][kseg][c]

#define FMA2(acc, a, b) asm("fma.rn.f32x2 %0, %1, %2, %0;" : "+l"(acc) : "l"(a), "l"(b))

// ---- fused-kernel smem layout (bytes). Per-CTA total ~110 KB -> 2 CTAs/SM ----------
#define SM_XW    0                                  // float[NV*FH]      65536
#define SM_W     (SM_XW   + NV*FH*4)                // float[FH*FI]       8192
#define SM_DINV  (SM_W    + FH*FI*4)                // float[NV]          2048
#define SM_ROWP  (SM_DINV + NV*4)                   // int[NV+1]          2052
#define SM_WTMP  ((SM_ROWP + (NV+1)*4 + 15) & ~15)  // int[16]
#define SM_UNION ((SM_WTMP + 64 + 15) & ~15)
#define SM_XSTG  SM_UNION                           // float[128*FI]     32768 (GEMM)
#define SM_OFFS  SM_UNION                           // int[NV]            2048 (CSR)
#define SM_CSR   (SM_OFFS + NV*4)                   // int[NE]           16384
#define SM_NRM   (SM_CSR  + NE*4)                   // float[NE]         16384
#define SMEM_TOT (SM_UNION + NE*4*2 + NV*4)         // 112720 B

// =====================================================================================
// Fused per-(graph, feature-half) kernel. 512 thr, 2 CTAs/SM (smem 110 KB, regs<=64).
//   A) GEMM xw_half = x @ W[fh*32:+32]^T in smem: 4 phases x 128 rows,
//      thread tile 4n x 2o, packed f32x2 over f, XOR-swizzled W (conflict-free).
//   B) CSR build (histogram/rsqrt/scan/scatter + edge norms) in union region.
//   C) Gather: warp per node (32/warp), lane owns 1 feature (LDS.32, bank-exact),
//      unroll x4; +bias, ReLU -> g_h[g][n][fh*32+lane].
// =====================================================================================
__global__ __launch_bounds__(512, 2) void k_fused(const float* __restrict__ x,
                                                  const float* __restrict__ W,
                                                  const int* __restrict__ eidx,
                                                  const float* __restrict__ cbias) {
    extern __shared__ char sm[];
    float* xw_s  = (float*)(sm + SM_XW);
    float* w_s   = (float*)(sm + SM_W);
    float* dinv  = (float*)(sm + SM_DINV);
    int*   rowptr= (int*)  (sm + SM_ROWP);
    int*   wtmp  = (int*)  (sm + SM_WTMP);
    float* xstg  = (float*)(sm + SM_XSTG);
    int*   offs  = (int*)  (sm + SM_OFFS);
    int*   csr   = (int*)  (sm + SM_CSR);
    float* nrmv  = (float*)(sm + SM_NRM);

    const int fh   = blockIdx.x;        // feature half 0/1
    const int g    = blockIdx.y;
    const int tid  = threadIdx.x;
    const int lane = tid & 31, wrp = tid >> 5;
    const int* srce = eidx + (size_t)g*2*NE;
    const int* tgte = srce + NE;

    // ---- load W half with pair-granular XOR swizzle ----
    for (int i = tid; i < FH*FI/2; i += 512) {
        int o  = i >> 5;                 // 0..31 local out row
        int fp = (i & 31) * 2;
        int fs = fp ^ (2*((o >> 1) & 15));
        *(unsigned long long*)&w_s[o*64 + fs] =
            *(const unsigned long long*)&W[(fh*FH + o)*FI + fp];
    }

    // ---- GEMM: 4 phases of 128 nodes ----
    const int tx = tid & 15;            // o-group (2 outs)
    const int ny = tid >> 4;            // n-group (4 rows), half-warp uniform
    const int nb = ny * 4, ob = tx * 2, sw = 2 * tx;

#pragma unroll 1
    for (int p = 0; p < 4; p++) {
        __syncthreads();                // xstg reuse boundary (covers w_s 1st time)
        const float4* xg4 = (const float4*)(x + ((size_t)g*NV + p*128) * FI);
        float4* xs4 = (float4*)xstg;
        for (int i = tid; i < 128*FI/4; i += 512) xs4[i] = xg4[i];
        __syncthreads();

        unsigned long long acc[4][2];
#pragma unroll
        for (int i = 0; i < 4; i++) { acc[i][0] = 0ull; acc[i][1] = 0ull; }

#pragma unroll
        for (int f = 0; f < 64; f += 4) {
            unsigned long long b0[2], b1[2];
#pragma unroll
            for (int j = 0; j < 2; j++) {
                b0[j] = *(const unsigned long long*)&w_s[(ob+j)*64 + ( f      ^ sw)];
                b1[j] = *(const unsigned long long*)&w_s[(ob+j)*64 + ((f + 2) ^ sw)];
            }
#pragma unroll
            for (int i = 0; i < 4; i++) {
                ulonglong2 a2 = *(const ulonglong2*)&xstg[(nb+i)*64 + f];
                FMA2(acc[i][0], a2.x, b0[0]);
                FMA2(acc[i][1], a2.x, b0[1]);
                FMA2(acc[i][0], a2.y, b1[0]);
                FMA2(acc[i][1], a2.y, b1[1]);
            }
        }
#pragma unroll
        for (int i = 0; i < 4; i++) {
            float2 o2;
            o2.x = __uint_as_float((unsigned)(acc[i][0] & 0xffffffffull))
                 + __uint_as_float((unsigned)(acc[i][0] >> 32));
            o2.y = __uint_as_float((unsigned)(acc[i][1] & 0xffffffffull))
                 + __uint_as_float((unsigned)(acc[i][1] >> 32));
            *(float2*)&xw_s[(p*128 + nb + i)*FH + ob] = o2;
        }
    }
    __syncthreads();                    // xw_s done; union region free for CSR

    // ---- in-degree histogram (512 thr == NV) ----
    offs[tid] = 0;
    __syncthreads();
#pragma unroll
    for (int e = tid; e < NE; e += 512) atomicAdd(&offs[tgte[e]], 1);
    __syncthreads();

    const int cnt = offs[tid];
    dinv[tid] = rsqrtf((float)(cnt + 1));   // +1 self-loop

    // ---- block exclusive scan (16 warps) ----
    int v = cnt;
#pragma unroll
    for (int d = 1; d < 32; d <<= 1) {
        int t = __shfl_up_sync(0xffffffffu, v, d);
        if (lane >= d) v += t;
    }
    if (lane == 31) wtmp[wrp] = v;
    __syncthreads();
    if (wrp == 0) {
        int wv = (lane < 16) ? wtmp[lane] : 0;
#pragma unroll
        for (int d = 1; d < 16; d <<= 1) {
            int t = __shfl_up_sync(0xffffffffu, wv, d);
            if (lane >= d) wv += t;
        }
        if (lane < 16) wtmp[lane] = wv;
    }
    __syncthreads();
    const int base = (wrp > 0) ? wtmp[wrp-1] : 0;
    const int excl = base + (v - cnt);
    rowptr[tid] = excl;
    offs[tid]   = excl;
    if (tid == 0) rowptr[NV] = NE;
    __syncthreads();

    // ---- scatter edges sorted by target; precompute edge norms ----
#pragma unroll
    for (int e = tid; e < NE; e += 512) {
        int s = srce[e], c = tgte[e];
        int p = atomicAdd(&offs[c], 1);
        csr[p]  = s;
        nrmv[p] = dinv[s] * dinv[c];
    }
    __syncthreads();

    // ---- gather: warp per node (32/warp), lane owns feature fh*32+lane ----
    const float bias = cbias[fh*FH + lane];
    for (int n = wrp*32; n < wrp*32 + 32; n++) {
        const float d = dinv[n];
        float a = xw_s[n*FH + lane] * (d*d);
        int j = rowptr[n];
        const int end = rowptr[n+1];
        for (; j + 4 <= end; j += 4) {
            int s0 = csr[j],   s1 = csr[j+1], s2 = csr[j+2], s3 = csr[j+3];
            float w0 = nrmv[j], w1 = nrmv[j+1], w2 = nrmv[j+2], w3 = nrmv[j+3];
            float m0 = xw_s[s0*FH + lane];
            float m1 = xw_s[s1*FH + lane];
            float m2 = xw_s[s2*FH + lane];
            float m3 = xw_s[s3*FH + lane];
            a = fmaf(m0, w0, a);
            a = fmaf(m1, w1, a);
            a = fmaf(m2, w2, a);
            a = fmaf(m3, w3, a);
        }
        for (; j < end; j++)
            a = fmaf(xw_s[csr[j]*FH + lane], nrmv[j], a);
        g_h[((size_t)g*NV + n)*FO + fh*FH + lane] = fmaxf(a + bias, 0.f);
    }
}

// =====================================================================================
// K3: logits split-K, weight-stationary. grid(16 graph-tiles, 64 k-chunks), 256 thr.
// warp w owns k-seg by*512 + w*64; lane = (c, kh); w[c][32k] packed f32x2 in regs;
// dual acc chains; loops 16 graphs. Deterministic partials -> g_part[g][seg][c].
// =====================================================================================
__global__ __launch_bounds__(256) void k_lin(const float* __restrict__ lw) {
    const int bx = blockIdx.x;
    const int by = blockIdx.y;
    const int tid = threadIdx.x;
    const int lane = tid & 31, wrp = tid >> 5;
    const int c  = lane & 15;
    const int kh = lane >> 4;
    const int kbase = by*512 + wrp*64 + kh*32;
    const int seg = by*8 + wrp;

    unsigned long long wreg[16];
    const float* wp = lw + (size_t)c*KFLAT + kbase;
#pragma unroll
    for (int p = 0; p < 16; p++)
        wreg[p] = *(const unsigned long long*)&wp[2*p];

    for (int gi = 0; gi < 16; gi++) {
        const int g = bx*16 + gi;
        const float* hp = g_h + (size_t)g*KFLAT + kbase;
        unsigned long long acc0 = 0ull, acc1 = 0ull;
#pragma unroll
        for (int p = 0; p < 4; p++) {
            ulonglong2 ha = *(const ulonglong2*)&hp[8*p];
            ulonglong2 hb = *(const ulonglong2*)&hp[8*p + 4];
            FMA2(acc0, ha.x, wreg[4*p    ]);
            FMA2(acc1, ha.y, wreg[4*p + 1]);
            FMA2(acc0, hb.x, wreg[4*p + 2]);
            FMA2(acc1, hb.y, wreg[4*p + 3]);
        }
        float s = __uint_as_float((unsigned)(acc0 & 0xffffffffull))
                + __uint_as_float((unsigned)(acc0 >> 32))
                + __uint_as_float((unsigned)(acc1 & 0xffffffffull))
                + __uint_as_float((unsigned)(acc1 >> 32));
        s += __shfl_xor_sync(0xffffffffu, s, 16);
        if (kh == 0)
            g_part[((size_t)g*512 + seg)*NC + c] = s;
    }
}

// =====================================================================================
// K4: one block per graph. float4 partial sums, smem tree, + bias, log_softmax.
// =====================================================================================
__global__ __launch_bounds__(256) void k_sm(const float* __restrict__ lbias,
                                            float* __restrict__ out) {
    __shared__ float red[64][16];
    const int g = blockIdx.x;
    const int t = threadIdx.x;
    const int quad = t & 3, sg = t >> 2;

    const float4* pp4 = (const float4*)(g_part + (size_t)g*512*NC);
    float4 acc = make_float4(0.f, 0.f, 0.f, 0.f);
#pragma unroll
    for (int s8 = 0; s8 < 8; s8++) {
        float4 v = pp4[(sg*8 + s8)*4 + quad];
        acc.x += v.x; acc.y += v.y; acc.z += v.z; acc.w += v.w;
    }
    *(float4*)&red[sg][quad*4] = acc;
    __syncthreads();

    if (t < 16) {
        float tot = lbias[t];
#pragma unroll 8
        for (int s = 0; s < 64; s++) tot += red[s][t];

        float m = tot;
#pragma unroll
        for (int d = 8; d >= 1; d >>= 1)
            m = fmaxf(m, __shfl_xor_sync(0x0000ffffu, m, d));
        float e = expf(tot - m);
#pragma unroll
        for (int d = 8; d >= 1; d >>= 1)
            e += __shfl_xor_sync(0x0000ffffu, e, d);

        out[(size_t)g*NC + t] = (tot - m) - logf(e);
    }
}

// =====================================================================================
extern "C" void kernel_launch(void* const* d_in, const int* in_sizes, int n_in,
                              void* d_out, int out_size) {
    const float* x  = (const float*)d_in[0];   // [G,NV,FI]
    const int*   ei = (const int*)  d_in[1];   // [G,2,NE]
    const float* cw = (const float*)d_in[2];   // [FO,FI]
    const float* cb = (const float*)d_in[3];   // [FO]
    const float* lw = (const float*)d_in[4];   // [NC,KFLAT]
    const float* lb = (const float*)d_in[5];   // [NC]
    float* out = (float*)d_out;                // [G,NC]

    (void)in_sizes; (void)n_in; (void)out_size;

    cudaFuncSetAttribute(k_fused, cudaFuncAttributeMaxDynamicSharedMemorySize, SMEM_TOT);

    k_fused<<<dim3(2, G), 512, SMEM_TOT>>>(x, cw, ei, cb);
    k_lin  <<<dim3(16, 64), 256>>>(lw);
    k_sm   <<<G, 256>>>(lb, out);
}